// round 3
// baseline (speedup 1.0000x reference)
#include <cuda_runtime.h>

#define THREADS 256
#define NBLOCKS 1184   // 8 CTAs/SM target on 148 SMs; grid-stride handles any occupancy

__global__ __launch_bounds__(THREADS)
void transh_score_pipe_kernel(
    const int* __restrict__ pos_h, const int* __restrict__ pos_t, const int* __restrict__ pos_r,
    const int* __restrict__ neg_h, const int* __restrict__ neg_t, const int* __restrict__ neg_r,
    const float4* __restrict__ ent,    // [ENT, 32] float4
    const float4* __restrict__ vvrel,  // [ENT, 32] float4
    const float4* __restrict__ bases,  // [REL, 32] float4
    float* __restrict__ out, int n)
{
    const int lane   = threadIdx.x & 31;
    const int stride = (gridDim.x * blockDim.x) >> 5;
    int i = (blockIdx.x * blockDim.x + threadIdx.x) >> 5;
    if (i >= n) return;

    // Prologue: indices for the first triple.
    int iph = __ldg(pos_h + i);
    int ipt = __ldg(pos_t + i);
    int ipr = __ldg(pos_r + i);
    int inh = __ldg(neg_h + i);
    int itt = __ldg(neg_t + i);
    int inr = __ldg(neg_r + i);

    for (;;) {
        // ---- Issue the 7 row gathers for triple i (addresses already known) ----
        const float4 v  = __ldg(bases + (size_t)ipr * 32 + lane);
        const float4 h  = __ldg(ent   + (size_t)iph * 32 + lane);
        const float4 t  = __ldg(ent   + (size_t)ipt * 32 + lane);
        const float4 r  = __ldg(vvrel + (size_t)ipr * 32 + lane);
        const float4 nh = __ldg(ent   + (size_t)inh * 32 + lane);
        const float4 nt = __ldg(ent   + (size_t)itt * 32 + lane);
        const float4 nr = __ldg(vvrel + (size_t)inr * 32 + lane);

        // ---- Prefetch indices for the NEXT triple (overlaps the gathers) ----
        const int j    = i + stride;
        const bool more = (j < n);
        const int jc   = more ? j : i;   // safe address when no next triple
        const int jph = __ldg(pos_h + jc);
        const int jpt = __ldg(pos_t + jc);
        const int jpr = __ldg(pos_r + jc);
        const int jnh = __ldg(neg_h + jc);
        const int jtt = __ldg(neg_t + jc);
        const int jnr = __ldg(neg_r + jc);

        // ---- Compute: P is linear & shared v  =>  sum|P(h)+P(r)-P(t)| = sum|P(h+r-t)| ----
        float4 dp, dn;
        dp.x = h.x + r.x - t.x;     dp.y = h.y + r.y - t.y;
        dp.z = h.z + r.z - t.z;     dp.w = h.w + r.w - t.w;
        dn.x = nh.x + nr.x - nt.x;  dn.y = nh.y + nr.y - nt.y;
        dn.z = nh.z + nr.z - nt.z;  dn.w = nh.w + nr.w - nt.w;

        float pvv = v.x * v.x  + v.y * v.y  + v.z * v.z  + v.w * v.w;
        float pvp = v.x * dp.x + v.y * dp.y + v.z * dp.z + v.w * dp.w;
        float pvn = v.x * dn.x + v.y * dn.y + v.z * dn.z + v.w * dn.w;
        #pragma unroll
        for (int o = 16; o > 0; o >>= 1) {
            pvv += __shfl_xor_sync(0xFFFFFFFFu, pvv, o);
            pvp += __shfl_xor_sync(0xFFFFFFFFu, pvp, o);
            pvn += __shfl_xor_sync(0xFFFFFFFFu, pvn, o);
        }
        const float inv_vv = 1.0f / pvv;
        const float cp = pvp * inv_vv;
        const float cn = pvn * inv_vv;

        float sp = fabsf(dp.x - cp * v.x) + fabsf(dp.y - cp * v.y)
                 + fabsf(dp.z - cp * v.z) + fabsf(dp.w - cp * v.w);
        float sn = fabsf(dn.x - cn * v.x) + fabsf(dn.y - cn * v.y)
                 + fabsf(dn.z - cn * v.z) + fabsf(dn.w - cn * v.w);
        #pragma unroll
        for (int o = 16; o > 0; o >>= 1) {
            sp += __shfl_xor_sync(0xFFFFFFFFu, sp, o);
            sn += __shfl_xor_sync(0xFFFFFFFFu, sn, o);
        }

        if (lane == 0) {
            out[i]     = sp;
            out[n + i] = sn;
        }

        if (!more) break;
        i = j;
        iph = jph; ipt = jpt; ipr = jpr;
        inh = jnh; itt = jtt; inr = jnr;
    }
}

extern "C" void kernel_launch(void* const* d_in, const int* in_sizes, int n_in,
                              void* d_out, int out_size)
{
    const int*    pos_h = (const int*)d_in[0];
    const int*    pos_t = (const int*)d_in[1];
    const int*    pos_r = (const int*)d_in[2];
    const int*    neg_h = (const int*)d_in[3];
    const int*    neg_t = (const int*)d_in[4];
    const int*    neg_r = (const int*)d_in[5];
    const float4* ent   = (const float4*)d_in[6];
    const float4* vvrel = (const float4*)d_in[7];
    const float4* bases = (const float4*)d_in[8];
    float* out = (float*)d_out;

    const int n = in_sizes[0];  // 65536 triples
    transh_score_pipe_kernel<<<NBLOCKS, THREADS>>>(
        pos_h, pos_t, pos_r, neg_h, neg_t, neg_r, ent, vvrel, bases, out, n);
}